// round 1
// baseline (speedup 1.0000x reference)
#include <cuda_runtime.h>
#include <math.h>

#define H 256
#define N_STATE 64
#define L 2048
#define BATCH 8

#define OT 512          // output tile (time)
#define MT 512          // input tile (time)
#define NTHREADS 64     // threads per conv block; each owns 8 consecutive outputs

// scratch (no allocation allowed)
__device__ float4 g_params[H * N_STATE];   // {Ceff_r, Ceff_i, dtA_r, dtA_i}
__device__ float  g_k[H * L];              // SSM convolution kernel

// ---------------------------------------------------------------------------
// Kernel 1: per-(h,n) parameters, replicating the reference's fp32 op order.
// ---------------------------------------------------------------------------
__global__ void s4d_params_kernel(const float* __restrict__ A_real,
                                  const float* __restrict__ A_imag,
                                  const float* __restrict__ Bm,
                                  const float* __restrict__ Cm,
                                  const float* __restrict__ inv_dt)
{
    int idx = blockIdx.x * blockDim.x + threadIdx.x;
    if (idx >= H * N_STATE) return;
    int h = idx / N_STATE;

    float Ar = -expf(A_real[idx]);          // A = -exp(A_real) - i*A_imag
    float Ai = -A_imag[idx];
    // dt via correctly-rounded double exp -> fp32 (tracks XLA's f32 exp)
    float dt = (float)exp((double)inv_dt[h]);
    float dtAr = dt * Ar;
    float dtAi = dt * Ai;

    // exp(dtA) - 1 ; |dtAi| <= ~20, use double sin/cos for full accuracy
    float er = expf(dtAr);
    double di = (double)dtAi;
    double sd, cd;
    sincos(di, &sd, &cd);
    float Er = fmaf(er, (float)cd, -1.0f);
    float Ei = er * (float)sd;

    float br = Bm[2 * idx], bi = Bm[2 * idx + 1];
    float cr = Cm[2 * idx], ci = Cm[2 * idx + 1];
    float bcr = br * cr - bi * ci;          // Bc*Cc
    float bci = br * ci + bi * cr;
    float tr = bcr * Er - bci * Ei;         // (Bc*Cc)*(exp(dtA)-1)
    float ti = bcr * Ei + bci * Er;
    float inv = 1.0f / (Ar * Ar + Ai * Ai); // .../A
    float cer = (tr * Ar + ti * Ai) * inv;
    float cei = (ti * Ar - tr * Ai) * inv;

    g_params[idx] = make_float4(cer, cei, dtAr, dtAi);
}

// ---------------------------------------------------------------------------
// Kernel 2: k[h,l] = 2 * sum_n Re(Ceff * exp(dtA_r*l) * cis(fl32(dtA_i*l)))
// Phase: theta computed as a single fp32 multiply (matches reference rounding),
// then reduced mod 2pi in double, then accurate fp32 quadrant polynomials
// (robust to -use_fast_math).
// ---------------------------------------------------------------------------
__global__ void s4d_kgen_kernel(void)
{
    __shared__ float4 sp[N_STATE];
    int h = blockIdx.y;
    int l = blockIdx.x * blockDim.x + threadIdx.x;
    if (threadIdx.x < N_STATE) sp[threadIdx.x] = g_params[h * N_STATE + threadIdx.x];
    __syncthreads();

    const double INV2PI = 0.15915494309189535;
    const double TWOPI  = 6.283185307179586;
    const float  TWO_OVER_PI = 0.6366197723675814f;
    const float  PIO2_HI = 1.57079637050628662109375f;   // (float)(pi/2)
    const float  PIO2_LO = -4.37113900018624283e-8f;     // pi/2 - PIO2_HI

    float fl = (float)l;
    float acc = 0.0f;

    #pragma unroll 4
    for (int n = 0; n < N_STATE; n++) {
        float4 p = sp[n];
        float theta = p.w * fl;                 // fp32 product — matches reference
        float decay = expf(p.z * fl);

        // reduce theta mod 2pi (double, exact enough: err ~1e-12 rad)
        double td = (double)theta;
        double qd = rint(td * INV2PI);
        float r = (float)fma(-qd, TWOPI, td);   // r in [-pi, pi]

        // quadrant reduction to [-pi/4, pi/4]
        float qf = rintf(r * TWO_OVER_PI);
        float rr = fmaf(-qf, PIO2_HI, r);
        rr = fmaf(-qf, PIO2_LO, rr);
        int qi = (int)qf & 3;

        float x2 = rr * rr;
        // sin poly (deg 9)
        float s = fmaf(x2, 2.75573192e-6f, -1.98412698e-4f);
        s = fmaf(x2, s, 8.33333333e-3f);
        s = fmaf(x2, s, -1.66666667e-1f);
        s = rr * fmaf(x2, s, 1.0f);
        // cos poly (deg 8)
        float c = fmaf(x2, 2.48015873e-5f, -1.38888889e-3f);
        c = fmaf(x2, c, 4.16666667e-2f);
        c = fmaf(x2, c, -0.5f);
        c = fmaf(x2, c, 1.0f);

        float S, C;
        switch (qi) {
            case 0: S = s;  C = c;  break;
            case 1: S = c;  C = -s; break;
            case 2: S = -s; C = -c; break;
            default: S = -c; C = s; break;
        }
        // 2*Re(Ceff * decay*(C + iS)) accumulated (x2 applied at the end)
        acc = fmaf(decay, fmaf(p.x, C, -p.y * S), acc);
    }
    g_k[h * L + l] = 2.0f * acc;
}

// ---------------------------------------------------------------------------
// Kernel 3: causal convolution y[b,h,l] = sum_{m<=l} k[l-m]*x[m], then ReLU.
// Block = (t-tile, h, b). 64 threads, each owns 8 consecutive outputs.
// k stored reversed in smem so the per-thread k window slides UP with m:
// steady state = 1 new LDS.128 (k) + 1 broadcast LDS.128 (x) per 32 FFMA.
// ---------------------------------------------------------------------------
__global__ void __launch_bounds__(NTHREADS)
s4d_conv_kernel(const float* __restrict__ x, float* __restrict__ y)
{
    __shared__ __align__(16) float xs[MT];
    __shared__ __align__(16) float ksh[OT + MT + 16];   // 1040 floats

    int t0 = blockIdx.x * OT;
    int h  = blockIdx.y;
    int b  = blockIdx.z;
    int tid = threadIdx.x;

    const float* xrow = x + (b * H + h) * L;
    const float* krow = g_k + h * L;

    float acc[8];
    #pragma unroll
    for (int j = 0; j < 8; j++) acc[j] = 0.0f;

    for (int m0 = 0; m0 <= t0; m0 += MT) {
        __syncthreads();
        #pragma unroll
        for (int i = tid; i < MT; i += NTHREADS) xs[i] = xrow[m0 + i];
        int qmax = t0 + OT - 1 - m0;
        #pragma unroll
        for (int i = tid; i < OT + MT + 16; i += NTHREADS) {
            int q = qmax - i;                          // lag l - m
            ksh[i] = (q >= 0) ? krow[q] : 0.0f;        // q <= 2047 always
        }
        __syncthreads();

        int ib0 = OT - 8 - 8 * tid;   // 16B-aligned (multiple of 8 floats)
        float4 kA = *(const float4*)&ksh[ib0];
        float4 kB = *(const float4*)&ksh[ib0 + 4];

        #pragma unroll 2
        for (int m = 0; m < MT; m += 4) {
            float4 kC = *(const float4*)&ksh[ib0 + m + 8];
            float4 xv = *(const float4*)&xs[m];
            // m+0
            acc[7] = fmaf(kA.x, xv.x, acc[7]);
            acc[6] = fmaf(kA.y, xv.x, acc[6]);
            acc[5] = fmaf(kA.z, xv.x, acc[5]);
            acc[4] = fmaf(kA.w, xv.x, acc[4]);
            acc[3] = fmaf(kB.x, xv.x, acc[3]);
            acc[2] = fmaf(kB.y, xv.x, acc[2]);
            acc[1] = fmaf(kB.z, xv.x, acc[1]);
            acc[0] = fmaf(kB.w, xv.x, acc[0]);
            // m+1
            acc[7] = fmaf(kA.y, xv.y, acc[7]);
            acc[6] = fmaf(kA.z, xv.y, acc[6]);
            acc[5] = fmaf(kA.w, xv.y, acc[5]);
            acc[4] = fmaf(kB.x, xv.y, acc[4]);
            acc[3] = fmaf(kB.y, xv.y, acc[3]);
            acc[2] = fmaf(kB.z, xv.y, acc[2]);
            acc[1] = fmaf(kB.w, xv.y, acc[1]);
            acc[0] = fmaf(kC.x, xv.y, acc[0]);
            // m+2
            acc[7] = fmaf(kA.z, xv.z, acc[7]);
            acc[6] = fmaf(kA.w, xv.z, acc[6]);
            acc[5] = fmaf(kB.x, xv.z, acc[5]);
            acc[4] = fmaf(kB.y, xv.z, acc[4]);
            acc[3] = fmaf(kB.z, xv.z, acc[3]);
            acc[2] = fmaf(kB.w, xv.z, acc[2]);
            acc[1] = fmaf(kC.x, xv.z, acc[1]);
            acc[0] = fmaf(kC.y, xv.z, acc[0]);
            // m+3
            acc[7] = fmaf(kA.w, xv.w, acc[7]);
            acc[6] = fmaf(kB.x, xv.w, acc[6]);
            acc[5] = fmaf(kB.y, xv.w, acc[5]);
            acc[4] = fmaf(kB.z, xv.w, acc[4]);
            acc[3] = fmaf(kB.w, xv.w, acc[3]);
            acc[2] = fmaf(kC.x, xv.w, acc[2]);
            acc[1] = fmaf(kC.y, xv.w, acc[1]);
            acc[0] = fmaf(kC.z, xv.w, acc[0]);
            kA = kB;
            kB = kC;
        }
    }

    float* yrow = y + (b * H + h) * L;
    #pragma unroll
    for (int j = 0; j < 8; j++) {
        float v = acc[j];
        yrow[t0 + 8 * tid + j] = v > 0.0f ? v : 0.0f;   // ReLU
    }
}

// ---------------------------------------------------------------------------
extern "C" void kernel_launch(void* const* d_in, const int* in_sizes, int n_in,
                              void* d_out, int out_size)
{
    const float* x      = (const float*)d_in[0];   // (B, H, L)
    const float* A_real = (const float*)d_in[1];   // (H, N)
    const float* A_imag = (const float*)d_in[2];   // (H, N)
    const float* Bm     = (const float*)d_in[3];   // (1, H, N, 2)
    const float* Cm     = (const float*)d_in[4];   // (1, H, N, 2)
    const float* inv_dt = (const float*)d_in[5];   // (H, 1)
    float* y = (float*)d_out;                      // (B, 1, H, L)

    s4d_params_kernel<<<(H * N_STATE + 255) / 256, 256>>>(A_real, A_imag, Bm, Cm, inv_dt);
    s4d_kgen_kernel<<<dim3(L / 256, H), 256>>>();
    s4d_conv_kernel<<<dim3(L / OT, H, BATCH), NTHREADS>>>(x, y);
}